// round 16
// baseline (speedup 1.0000x reference)
#include <cuda_runtime.h>
#include <cuda_bf16.h>
#include <cstdint>

// Problem constants
#define NB   32
#define DIM  256
#define HWD  1024
#define NV   (NB*HWD)        // 32768 vectors
#define NK   1024            // codes
#define NELEM (NV*DIM)

// Scratch
__device__ float                   g_flat[NV * DIM];       // z transposed [vec, d] fp32
__device__ __align__(16) __nv_bfloat16 g_flat_bf16[NV * DIM];  // bf16 copy (A tiles)
__device__ __align__(16) uint32_t  g_emb_bf16[NK * 128];   // bf16x2 codebook (B tiles)
__device__ float                   g_ee[NK];               // ||e_k||^2
__device__ __align__(16) uint32_t  g_y_u32[NV * (NK/2)];   // y = ee - 2*dot, bf16x2 packed
__device__ int                     g_win[NV];              // winning code per row
__device__ double                  g_loss_sum;
__device__ unsigned                g_done = 0;             // gather completion counter

// ===========================================================================
__device__ __forceinline__ uint32_t smem_u32(const void* p) {
    uint32_t a;
    asm("{ .reg .u64 t; cvta.to.shared.u64 t, %1; cvt.u32.u64 %0, t; }" : "=r"(a) : "l"(p));
    return a;
}
#define CP_ASYNC16(d, s) asm volatile("cp.async.cg.shared.global [%0], [%1], 16;" :: "r"(d), "l"(s))
#define CP_COMMIT()      asm volatile("cp.async.commit_group;" ::: "memory")
#define CP_WAIT0()       asm volatile("cp.async.wait_group 0;" ::: "memory")
#define LDMX4(r, a) \
    asm volatile("ldmatrix.sync.aligned.m8n8.x4.shared.b16 {%0,%1,%2,%3}, [%4];" \
        : "=r"((r)[0]), "=r"((r)[1]), "=r"((r)[2]), "=r"((r)[3]) : "r"(a))
#define LDMX2(r, a) \
    asm volatile("ldmatrix.sync.aligned.m8n8.x2.shared.b16 {%0,%1}, [%2];" \
        : "=r"((r)[0]), "=r"((r)[1]) : "r"(a))

__device__ __forceinline__ __nv_bfloat162 u2b(uint32_t u) {
    return *reinterpret_cast<__nv_bfloat162*>(&u);
}
__device__ __forceinline__ uint32_t b2u(__nv_bfloat162 b) {
    return *reinterpret_cast<uint32_t*>(&b);
}

// ===========================================================================
// Transpose NCHW -> [vec, d]; also emit bf16 copy for MMA A tiles.
__global__ void vq_transpose_kernel(const float* __restrict__ z) {
    __shared__ float t[32][33];
    const int p0 = blockIdx.x * 32, d0 = blockIdx.y * 32, b = blockIdx.z;
    const int x = threadIdx.x, y = threadIdx.y;
#pragma unroll
    for (int j = 0; j < 32; j += 8)
        t[y + j][x] = z[b * (DIM * HWD) + (d0 + y + j) * HWD + p0 + x];
    __syncthreads();
#pragma unroll
    for (int j = 0; j < 32; j += 8) {
        const float v = t[x][y + j];
        const size_t o = (size_t)(b * HWD + p0 + y + j) * DIM + d0 + x;
        g_flat[o] = v;
        g_flat_bf16[o] = __float2bfloat16(v);
    }
}

// Codebook norms + bf16 codebook + loss zero. One warp per code.
__global__ void vq_enorm_kernel(const float* __restrict__ emb) {
    const int k = blockIdx.x, lane = threadIdx.x;
    if (k == 0 && lane == 0) g_loss_sum = 0.0;
    const float4* r4 = reinterpret_cast<const float4*>(emb + k * DIM);
    float4 a = r4[lane], b = r4[lane + 32];
    uint32_t* dst = g_emb_bf16 + k * 128;
    __nv_bfloat162 p;
    p = __float22bfloat162_rn(make_float2(a.x, a.y)); dst[lane*2]      = b2u(p);
    p = __float22bfloat162_rn(make_float2(a.z, a.w)); dst[lane*2+1]    = b2u(p);
    p = __float22bfloat162_rn(make_float2(b.x, b.y)); dst[64+lane*2]   = b2u(p);
    p = __float22bfloat162_rn(make_float2(b.z, b.w)); dst[64+lane*2+1] = b2u(p);
    float s = a.x*a.x + a.y*a.y + a.z*a.z + a.w*a.w
            + b.x*b.x + b.y*b.y + b.z*b.z + b.w*b.w;
#pragma unroll
    for (int off = 16; off; off >>= 1) s += __shfl_xor_sync(0xffffffffu, s, off);
    if (lane == 0) g_ee[k] = s;
}

// ===========================================================================
// bf16 mma.sync GEMM (R9-proven main loop, verbatim) + fused post-loop scan:
// per-row min kept in smem, then each warp filters+rescores 16 of the CTA's
// own rows against its freshly written (L2-hot) y data.
// ===========================================================================
#define SM_PITCH 528                      // bytes per padded bf16 row
#define TILE_BYTES (128 * SM_PITCH)       // 67584
#define GEMM_SMEM (3 * TILE_BYTES)        // A + 2x B

__device__ __forceinline__ void mma_bf16(float& c0, float& c1, float& c2, float& c3,
                                         uint32_t a0, uint32_t a1, uint32_t a2, uint32_t a3,
                                         uint32_t b0, uint32_t b1) {
    asm volatile(
        "mma.sync.aligned.m16n8k16.row.col.f32.bf16.bf16.f32 "
        "{%0,%1,%2,%3}, {%4,%5,%6,%7}, {%8,%9}, {%0,%1,%2,%3};"
        : "+f"(c0), "+f"(c1), "+f"(c2), "+f"(c3)
        : "r"(a0), "r"(a1), "r"(a2), "r"(a3), "r"(b0), "r"(b1));
}

__device__ __forceinline__ void fill_async(uint32_t tile_s, const char* __restrict__ src, int tid) {
#pragma unroll
    for (int i = tid; i < 4096; i += 256) {
        const int row = i >> 5, ch = (i & 31) << 4;
        CP_ASYNC16(tile_s + row * SM_PITCH + ch, src + row * 512 + ch);
    }
}

__global__ __launch_bounds__(256, 1) void vq_gemm_kernel(const float* __restrict__ emb) {
    extern __shared__ char sm[];
    __shared__ float s_ee[NK];
    __shared__ float s_pmin[128][4];
    __shared__ float s_ymin[128];
    const uint32_t aA  = smem_u32(sm);
    const uint32_t aB0 = aA + TILE_BYTES;
    const uint32_t aB1 = aA + 2 * TILE_BYTES;

    const int tid  = threadIdx.x;
    const int lane = tid & 31;
    const int wid  = tid >> 5;
    const int warp_m = wid & 1;
    const int warp_n = wid >> 1;
    const int g   = lane >> 2;
    const int tig = lane & 3;
    const int m0  = blockIdx.x * 128;

    fill_async(aA,  (const char*)g_flat_bf16 + (size_t)m0 * 512, tid);
    fill_async(aB0, (const char*)g_emb_bf16, tid);
    CP_COMMIT();
#pragma unroll
    for (int i = tid; i < NK; i += 256) s_ee[i] = g_ee[i];
    CP_WAIT0();
    __syncthreads();

    const int l7 = lane & 7, lm8 = (lane >> 3) & 1, lm16 = lane >> 4;
    uint32_t aAddr[4];
#pragma unroll
    for (int mf = 0; mf < 4; mf++)
        aAddr[mf] = aA + (uint32_t)((warp_m * 64 + mf * 16 + l7 + lm8 * 8) * SM_PITCH + lm16 * 16);
    uint32_t bRow[4];
#pragma unroll
    for (int nf = 0; nf < 4; nf++)
        bRow[nf] = (uint32_t)((warp_n * 32 + nf * 8 + l7) * SM_PITCH + lm8 * 16);

    const uint32_t infbits = 0x7F807F80u;
    uint32_t mlo[4], mhi[4];
#pragma unroll
    for (int mf = 0; mf < 4; mf++) { mlo[mf] = infbits; mhi[mf] = infbits; }

    for (int t = 0; t < 8; t++) {
        const uint32_t bBase = (t & 1) ? aB1 : aB0;
        if (t < 7) {
            fill_async(((t + 1) & 1) ? aB1 : aB0,
                       (const char*)g_emb_bf16 + (size_t)(t + 1) * 65536, tid);
            CP_COMMIT();
        }

        float acc[4][4][4];
#pragma unroll
        for (int mf = 0; mf < 4; mf++)
#pragma unroll
            for (int nf = 0; nf < 4; nf++)
#pragma unroll
                for (int c = 0; c < 4; c++) acc[mf][nf][c] = 0.f;

#pragma unroll
        for (int ks = 0; ks < 16; ks++) {
            const uint32_t kb = ks * 32;
            uint32_t a[4][4], b[4][2];
#pragma unroll
            for (int mf = 0; mf < 4; mf++) LDMX4(a[mf], aAddr[mf] + kb);
#pragma unroll
            for (int nf = 0; nf < 4; nf++) LDMX2(b[nf], bBase + bRow[nf] + kb);
#pragma unroll
            for (int mf = 0; mf < 4; mf++)
#pragma unroll
                for (int nf = 0; nf < 4; nf++)
                    mma_bf16(acc[mf][nf][0], acc[mf][nf][1], acc[mf][nf][2], acc[mf][nf][3],
                             a[mf][0], a[mf][1], a[mf][2], a[mf][3],
                             b[nf][0], b[nf][1]);
        }

#pragma unroll
        for (int mf = 0; mf < 4; mf++) {
            const int row0 = m0 + warp_m * 64 + mf * 16 + g;
#pragma unroll
            for (int nf = 0; nf < 4; nf++) {
                const int c0 = t * 128 + warp_n * 32 + nf * 8 + tig * 2;
                const float e0 = s_ee[c0], e1 = s_ee[c0 + 1];
                const int cp = c0 >> 1;
                __nv_bfloat162 lo = __float22bfloat162_rn(
                    make_float2(__fmaf_rn(-2.f, acc[mf][nf][0], e0),
                                __fmaf_rn(-2.f, acc[mf][nf][1], e1)));
                __nv_bfloat162 hi = __float22bfloat162_rn(
                    make_float2(__fmaf_rn(-2.f, acc[mf][nf][2], e0),
                                __fmaf_rn(-2.f, acc[mf][nf][3], e1)));
                g_y_u32[(size_t)row0 * (NK/2) + cp]       = b2u(lo);
                g_y_u32[(size_t)(row0 + 8) * (NK/2) + cp] = b2u(hi);
                mlo[mf] = b2u(__hmin2(u2b(mlo[mf]), lo));
                mhi[mf] = b2u(__hmin2(u2b(mhi[mf]), hi));
            }
        }

        if (t < 7) CP_WAIT0();
        __syncthreads();
    }

    // final per-row min: quad shuffle, cross-warp smem tree -> s_ymin
#pragma unroll
    for (int mf = 0; mf < 4; mf++) {
        uint32_t v = mlo[mf];
        v = b2u(__hmin2(u2b(v), u2b(__shfl_xor_sync(0xffffffffu, v, 1))));
        v = b2u(__hmin2(u2b(v), u2b(__shfl_xor_sync(0xffffffffu, v, 2))));
        uint32_t w = mhi[mf];
        w = b2u(__hmin2(u2b(w), u2b(__shfl_xor_sync(0xffffffffu, w, 1))));
        w = b2u(__hmin2(u2b(w), u2b(__shfl_xor_sync(0xffffffffu, w, 2))));
        if (tig == 0) {
            const float2 f1 = __bfloat1622float2(u2b(v));
            const float2 f2 = __bfloat1622float2(u2b(w));
            s_pmin[warp_m * 64 + mf * 16 + g][warp_n]     = fminf(f1.x, f1.y);
            s_pmin[warp_m * 64 + mf * 16 + g + 8][warp_n] = fminf(f2.x, f2.y);
        }
    }
    __syncthreads();
    if (tid < 128)
        s_ymin[tid] = fminf(fminf(s_pmin[tid][0], s_pmin[tid][1]),
                            fminf(s_pmin[tid][2], s_pmin[tid][3]));
    __syncthreads();   // also makes this CTA's global y-writes visible CTA-wide

    // ---- fused scan phase: each warp filters+rescores 16 of this CTA's rows
    // (R15-proven numerics: same mask build, same margin, same exact rescore)
#pragma unroll 1
    for (int j = 0; j < 16; j++) {
        const int r   = wid * 16 + j;
        const int row = m0 + r;
        const uint4* drow4 = reinterpret_cast<const uint4*>(g_y_u32 + (size_t)row * (NK / 2));
        const float4* x4 = reinterpret_cast<const float4*>(g_flat + (size_t)row * DIM);
        const float4 xa = x4[lane], xb = x4[lane + 32];
        const uint4 v0 = __ldg(drow4 + lane);
        const uint4 v1 = __ldg(drow4 + 32 + lane);
        const uint4 v2 = __ldg(drow4 + 64 + lane);
        const uint4 v3 = __ldg(drow4 + 96 + lane);

        // xx: identical expression + shfl tree as proven row_norm2
        float xx = xa.x*xa.x + xa.y*xa.y + xa.z*xa.z + xa.w*xa.w
                 + xb.x*xb.x + xb.y*xb.y + xb.z*xb.z + xb.w*xb.w;
#pragma unroll
        for (int off = 16; off; off >>= 1) xx += __shfl_xor_sync(0xffffffffu, xx, off);

        // rigorous margin: 12*2^-9 * ||x|| * ||e||max + slack (||e|| < 1/64)
        const float margin = sqrtf(xx) * 0.015625f * (12.0f / 512.0f) + 3e-4f;
        const float thr = s_ymin[r] + margin;

        const uint32_t comp[16] = {v0.x, v0.y, v0.z, v0.w, v1.x, v1.y, v1.z, v1.w,
                                   v2.x, v2.y, v2.z, v2.w, v3.x, v3.y, v3.z, v3.w};
        uint32_t mask = 0;
#pragma unroll
        for (int q = 0; q < 16; q++) {
            const float2 d = __bfloat1622float2(u2b(comp[q]));
            if (d.x <= thr) mask |= 1u << (2 * q);
            if (d.y <= thr) mask |= 1u << (2 * q + 1);
        }

        unsigned long long best = ~0ull;
        unsigned any = __ballot_sync(0xffffffffu, mask != 0);
        while (any) {
            const int lsrc = __ffs(any) - 1; any &= any - 1;
            uint32_t m = __shfl_sync(0xffffffffu, mask, lsrc);
            while (m) {
                const int bit = __ffs(m) - 1; m &= m - 1;
                const int code = ((bit >> 3) << 8) + (lsrc << 3) + (bit & 7);
                const float4* e4 = reinterpret_cast<const float4*>(emb + (size_t)code * DIM);
                const float4 ea = e4[lane], eb = e4[lane + 32];
                float s = xa.x * ea.x;
                s = fmaf(xa.y, ea.y, s); s = fmaf(xa.z, ea.z, s); s = fmaf(xa.w, ea.w, s);
                s = fmaf(xb.x, eb.x, s); s = fmaf(xb.y, eb.y, s);
                s = fmaf(xb.z, eb.z, s); s = fmaf(xb.w, eb.w, s);
#pragma unroll
                for (int off = 16; off; off >>= 1) s += __shfl_xor_sync(0xffffffffu, s, off);
                const float d2 = __fadd_rn(__fmaf_rn(-2.0f, s, xx), g_ee[code]);
                const unsigned long long key =
                    ((unsigned long long)__float_as_uint(d2) << 32) | (unsigned)code;
                best = (key < best) ? key : best;
            }
        }
        if (lane == 0) g_win[row] = (int)(best & 0xffffffffu);
    }
}

// ===========================================================================
// Gather + straight-through output + loss + fused finalize (R15-proven).
// FR=32 rows/block, dt-loop split across blockIdx.y (2048 blocks, 8 phases).
// ===========================================================================
#define FR 32

__global__ __launch_bounds__(256) void vq_gather_kernel(const float* __restrict__ emb,
                                                        float* __restrict__ out) {
    __shared__ int   s_idx[FR];
    __shared__ float tbuf[32][33];
    __shared__ float wsum[8];

    const int m0  = blockIdx.x * FR;
    const int dt0 = blockIdx.y * 128;     // this block's 128-dim half
    const int tid = threadIdx.x;
    if (tid < FR) s_idx[tid] = g_win[m0 + tid];
    __syncthreads();

    const int b_img = m0 >> 10;
    const int hw0   = m0 & (HWD - 1);
    const int dx = tid & 31;
    const int wy = tid >> 5;
    float lsum = 0.f;

    for (int dtl = 0; dtl < 128; dtl += 32) {
        const int dt = dt0 + dtl;
#pragma unroll
        for (int vv = 0; vv < FR; vv += 8) {
            const int v    = vv + wy;
            const int code = s_idx[v];
            const float e  = emb[code * DIM + dt + dx];
            const float x  = g_flat[(size_t)(m0 + v) * DIM + dt + dx];
            const float df = __fadd_rn(e, -x);
            lsum += df * df;
            tbuf[vv + wy][dx] = __fadd_rn(x, df);
        }
        __syncthreads();
#pragma unroll
        for (int dd = 0; dd < 32; dd += 8) {
            const int d = dt + dd + wy;
            out[(b_img * DIM + d) * HWD + hw0 + dx] = tbuf[dx][dd + wy];
        }
        __syncthreads();
    }

#pragma unroll
    for (int off = 16; off; off >>= 1) lsum += __shfl_xor_sync(0xffffffffu, lsum, off);
    if ((tid & 31) == 0) wsum[tid >> 5] = lsum;
    __syncthreads();
    if (tid == 0) {
        float tot = 0.f;
#pragma unroll
        for (int w = 0; w < 8; w++) tot += wsum[w];
        atomicAdd(&g_loss_sum, (double)tot);
        __threadfence();
        const unsigned done = atomicAdd(&g_done, 1u);
        if (done == (unsigned)(gridDim.x * gridDim.y - 1)) {
            __threadfence();
            const double total = atomicAdd(&g_loss_sum, 0.0);  // ordered read
            const float cb = (float)(total * (1.0 / (double)NELEM));
            out[NELEM + 0] = cb + 0.25f * cb;
            out[NELEM + 1] = cb;
            out[NELEM + 2] = cb;
            g_done = 0;  // reset for next graph replay
        }
    }
}

// ===========================================================================
extern "C" void kernel_launch(void* const* d_in, const int* in_sizes, int n_in,
                              void* d_out, int out_size) {
    const float* z   = (const float*)d_in[0];
    const float* emb = (const float*)d_in[1];
    if (n_in >= 2 && in_sizes[0] == NK * DIM && in_sizes[1] == NELEM) {
        const float* t = z; z = emb; emb = t;
    }
    float* out = (float*)d_out;

    cudaFuncSetAttribute(vq_gemm_kernel,
                         cudaFuncAttributeMaxDynamicSharedMemorySize, GEMM_SMEM);

    vq_transpose_kernel<<<dim3(HWD / 32, DIM / 32, NB), dim3(32, 8)>>>(z);
    vq_enorm_kernel<<<NK, 32>>>(emb);
    vq_gemm_kernel<<<NV / 128, 256, GEMM_SMEM>>>(emb);
    vq_gather_kernel<<<dim3(NV / FR, 2), 256>>>(emb, out);
}

// round 17
// speedup vs baseline: 1.3635x; 1.3635x over previous
#include <cuda_runtime.h>
#include <cuda_bf16.h>
#include <cstdint>

// Problem constants
#define NB   32
#define DIM  256
#define HWD  1024
#define NV   (NB*HWD)        // 32768 vectors
#define NK   1024            // codes
#define NELEM (NV*DIM)

// Scratch
__device__ float                   g_flat[NV * DIM];       // z transposed [vec, d] fp32
__device__ __align__(16) __nv_bfloat16 g_flat_bf16[NV * DIM];  // bf16 copy (A tiles)
__device__ __align__(16) uint32_t  g_emb_bf16[NK * 128];   // bf16x2 codebook (B tiles)
__device__ float                   g_ee[NK];               // ||e_k||^2
__device__ __align__(16) uint32_t  g_y_u32[NV * (NK/2)];   // y = ee - 2*dot, bf16x2 packed
__device__ float                   g_ymin[NV];             // per-row min of bf16 y
__device__ int                     g_win[NV];              // winning code per row
__device__ double                  g_loss_sum;
__device__ unsigned                g_done = 0;             // gather completion counter

// ===========================================================================
__device__ __forceinline__ uint32_t smem_u32(const void* p) {
    uint32_t a;
    asm("{ .reg .u64 t; cvta.to.shared.u64 t, %1; cvt.u32.u64 %0, t; }" : "=r"(a) : "l"(p));
    return a;
}
#define CP_ASYNC16(d, s) asm volatile("cp.async.cg.shared.global [%0], [%1], 16;" :: "r"(d), "l"(s))
#define CP_COMMIT()      asm volatile("cp.async.commit_group;" ::: "memory")
#define CP_WAIT0()       asm volatile("cp.async.wait_group 0;" ::: "memory")
#define LDMX4(r, a) \
    asm volatile("ldmatrix.sync.aligned.m8n8.x4.shared.b16 {%0,%1,%2,%3}, [%4];" \
        : "=r"((r)[0]), "=r"((r)[1]), "=r"((r)[2]), "=r"((r)[3]) : "r"(a))
#define LDMX2(r, a) \
    asm volatile("ldmatrix.sync.aligned.m8n8.x2.shared.b16 {%0,%1}, [%2];" \
        : "=r"((r)[0]), "=r"((r)[1]) : "r"(a))

__device__ __forceinline__ __nv_bfloat162 u2b(uint32_t u) {
    return *reinterpret_cast<__nv_bfloat162*>(&u);
}
__device__ __forceinline__ uint32_t b2u(__nv_bfloat162 b) {
    return *reinterpret_cast<uint32_t*>(&b);
}

// ===========================================================================
// Transpose NCHW -> [vec, d]; also emit bf16 copy for MMA A tiles.
__global__ void vq_transpose_kernel(const float* __restrict__ z) {
    __shared__ float t[32][33];
    const int p0 = blockIdx.x * 32, d0 = blockIdx.y * 32, b = blockIdx.z;
    const int x = threadIdx.x, y = threadIdx.y;
#pragma unroll
    for (int j = 0; j < 32; j += 8)
        t[y + j][x] = z[b * (DIM * HWD) + (d0 + y + j) * HWD + p0 + x];
    __syncthreads();
#pragma unroll
    for (int j = 0; j < 32; j += 8) {
        const float v = t[x][y + j];
        const size_t o = (size_t)(b * HWD + p0 + y + j) * DIM + d0 + x;
        g_flat[o] = v;
        g_flat_bf16[o] = __float2bfloat16(v);
    }
}

// Codebook norms + bf16 codebook + loss zero. One warp per code.
__global__ void vq_enorm_kernel(const float* __restrict__ emb) {
    const int k = blockIdx.x, lane = threadIdx.x;
    if (k == 0 && lane == 0) g_loss_sum = 0.0;
    const float4* r4 = reinterpret_cast<const float4*>(emb + k * DIM);
    float4 a = r4[lane], b = r4[lane + 32];
    uint32_t* dst = g_emb_bf16 + k * 128;
    __nv_bfloat162 p;
    p = __float22bfloat162_rn(make_float2(a.x, a.y)); dst[lane*2]      = b2u(p);
    p = __float22bfloat162_rn(make_float2(a.z, a.w)); dst[lane*2+1]    = b2u(p);
    p = __float22bfloat162_rn(make_float2(b.x, b.y)); dst[64+lane*2]   = b2u(p);
    p = __float22bfloat162_rn(make_float2(b.z, b.w)); dst[64+lane*2+1] = b2u(p);
    float s = a.x*a.x + a.y*a.y + a.z*a.z + a.w*a.w
            + b.x*b.x + b.y*b.y + b.z*b.z + b.w*b.w;
#pragma unroll
    for (int off = 16; off; off >>= 1) s += __shfl_xor_sync(0xffffffffu, s, off);
    if (lane == 0) g_ee[k] = s;
}

// ===========================================================================
// bf16 mma.sync GEMM (R9-proven, verbatim): ldmatrix loads, cp.async
// double-buffered B, y = fl(ee - 2*dot) bf16x2 store + register row-min.
// ===========================================================================
#define SM_PITCH 528                      // bytes per padded bf16 row
#define TILE_BYTES (128 * SM_PITCH)       // 67584
#define GEMM_SMEM (3 * TILE_BYTES)        // A + 2x B

__device__ __forceinline__ void mma_bf16(float& c0, float& c1, float& c2, float& c3,
                                         uint32_t a0, uint32_t a1, uint32_t a2, uint32_t a3,
                                         uint32_t b0, uint32_t b1) {
    asm volatile(
        "mma.sync.aligned.m16n8k16.row.col.f32.bf16.bf16.f32 "
        "{%0,%1,%2,%3}, {%4,%5,%6,%7}, {%8,%9}, {%0,%1,%2,%3};"
        : "+f"(c0), "+f"(c1), "+f"(c2), "+f"(c3)
        : "r"(a0), "r"(a1), "r"(a2), "r"(a3), "r"(b0), "r"(b1));
}

__device__ __forceinline__ void fill_async(uint32_t tile_s, const char* __restrict__ src, int tid) {
#pragma unroll
    for (int i = tid; i < 4096; i += 256) {
        const int row = i >> 5, ch = (i & 31) << 4;
        CP_ASYNC16(tile_s + row * SM_PITCH + ch, src + row * 512 + ch);
    }
}

__global__ __launch_bounds__(256, 1) void vq_gemm_kernel() {
    extern __shared__ char sm[];
    __shared__ float s_ee[NK];
    __shared__ float s_pmin[128][4];
    const uint32_t aA  = smem_u32(sm);
    const uint32_t aB0 = aA + TILE_BYTES;
    const uint32_t aB1 = aA + 2 * TILE_BYTES;

    const int tid  = threadIdx.x;
    const int lane = tid & 31;
    const int wid  = tid >> 5;
    const int warp_m = wid & 1;
    const int warp_n = wid >> 1;
    const int g   = lane >> 2;
    const int tig = lane & 3;
    const int m0  = blockIdx.x * 128;

    fill_async(aA,  (const char*)g_flat_bf16 + (size_t)m0 * 512, tid);
    fill_async(aB0, (const char*)g_emb_bf16, tid);
    CP_COMMIT();
#pragma unroll
    for (int i = tid; i < NK; i += 256) s_ee[i] = g_ee[i];
    CP_WAIT0();
    __syncthreads();

    const int l7 = lane & 7, lm8 = (lane >> 3) & 1, lm16 = lane >> 4;
    uint32_t aAddr[4];
#pragma unroll
    for (int mf = 0; mf < 4; mf++)
        aAddr[mf] = aA + (uint32_t)((warp_m * 64 + mf * 16 + l7 + lm8 * 8) * SM_PITCH + lm16 * 16);
    uint32_t bRow[4];
#pragma unroll
    for (int nf = 0; nf < 4; nf++)
        bRow[nf] = (uint32_t)((warp_n * 32 + nf * 8 + l7) * SM_PITCH + lm8 * 16);

    const uint32_t infbits = 0x7F807F80u;
    uint32_t mlo[4], mhi[4];
#pragma unroll
    for (int mf = 0; mf < 4; mf++) { mlo[mf] = infbits; mhi[mf] = infbits; }

    for (int t = 0; t < 8; t++) {
        const uint32_t bBase = (t & 1) ? aB1 : aB0;
        if (t < 7) {
            fill_async(((t + 1) & 1) ? aB1 : aB0,
                       (const char*)g_emb_bf16 + (size_t)(t + 1) * 65536, tid);
            CP_COMMIT();
        }

        float acc[4][4][4];
#pragma unroll
        for (int mf = 0; mf < 4; mf++)
#pragma unroll
            for (int nf = 0; nf < 4; nf++)
#pragma unroll
                for (int c = 0; c < 4; c++) acc[mf][nf][c] = 0.f;

#pragma unroll
        for (int ks = 0; ks < 16; ks++) {
            const uint32_t kb = ks * 32;
            uint32_t a[4][4], b[4][2];
#pragma unroll
            for (int mf = 0; mf < 4; mf++) LDMX4(a[mf], aAddr[mf] + kb);
#pragma unroll
            for (int nf = 0; nf < 4; nf++) LDMX2(b[nf], bBase + bRow[nf] + kb);
#pragma unroll
            for (int mf = 0; mf < 4; mf++)
#pragma unroll
                for (int nf = 0; nf < 4; nf++)
                    mma_bf16(acc[mf][nf][0], acc[mf][nf][1], acc[mf][nf][2], acc[mf][nf][3],
                             a[mf][0], a[mf][1], a[mf][2], a[mf][3],
                             b[nf][0], b[nf][1]);
        }

#pragma unroll
        for (int mf = 0; mf < 4; mf++) {
            const int row0 = m0 + warp_m * 64 + mf * 16 + g;
#pragma unroll
            for (int nf = 0; nf < 4; nf++) {
                const int c0 = t * 128 + warp_n * 32 + nf * 8 + tig * 2;
                const float e0 = s_ee[c0], e1 = s_ee[c0 + 1];
                const int cp = c0 >> 1;
                __nv_bfloat162 lo = __float22bfloat162_rn(
                    make_float2(__fmaf_rn(-2.f, acc[mf][nf][0], e0),
                                __fmaf_rn(-2.f, acc[mf][nf][1], e1)));
                __nv_bfloat162 hi = __float22bfloat162_rn(
                    make_float2(__fmaf_rn(-2.f, acc[mf][nf][2], e0),
                                __fmaf_rn(-2.f, acc[mf][nf][3], e1)));
                g_y_u32[(size_t)row0 * (NK/2) + cp]       = b2u(lo);
                g_y_u32[(size_t)(row0 + 8) * (NK/2) + cp] = b2u(hi);
                mlo[mf] = b2u(__hmin2(u2b(mlo[mf]), lo));
                mhi[mf] = b2u(__hmin2(u2b(mhi[mf]), hi));
            }
        }

        if (t < 7) CP_WAIT0();
        __syncthreads();
    }

#pragma unroll
    for (int mf = 0; mf < 4; mf++) {
        uint32_t v = mlo[mf];
        v = b2u(__hmin2(u2b(v), u2b(__shfl_xor_sync(0xffffffffu, v, 1))));
        v = b2u(__hmin2(u2b(v), u2b(__shfl_xor_sync(0xffffffffu, v, 2))));
        uint32_t w = mhi[mf];
        w = b2u(__hmin2(u2b(w), u2b(__shfl_xor_sync(0xffffffffu, w, 1))));
        w = b2u(__hmin2(u2b(w), u2b(__shfl_xor_sync(0xffffffffu, w, 2))));
        if (tig == 0) {
            const float2 f1 = __bfloat1622float2(u2b(v));
            const float2 f2 = __bfloat1622float2(u2b(w));
            s_pmin[warp_m * 64 + mf * 16 + g][warp_n]     = fminf(f1.x, f1.y);
            s_pmin[warp_m * 64 + mf * 16 + g + 8][warp_n] = fminf(f2.x, f2.y);
        }
    }
    __syncthreads();
    if (tid < 128)
        g_ymin[m0 + tid] = fminf(fminf(s_pmin[tid][0], s_pmin[tid][1]),
                                 fminf(s_pmin[tid][2], s_pmin[tid][3]));
}

// ===========================================================================
// Scan (R15-proven, verbatim): warp per row, all loads upfront, per-lane
// candidate bitmask + one ballot; exact fp32 rescore.
// ===========================================================================
__global__ __launch_bounds__(256) void vq_scan_kernel(const float* __restrict__ emb) {
    const int row  = blockIdx.x * 8 + (threadIdx.x >> 5);
    const int lane = threadIdx.x & 31;
    const uint4* drow4 = reinterpret_cast<const uint4*>(g_y_u32 + (size_t)row * (NK / 2));

    const float4* x4 = reinterpret_cast<const float4*>(g_flat + (size_t)row * DIM);
    const float4 xa = x4[lane], xb = x4[lane + 32];
    const uint4 v0 = __ldg(drow4 + lane);
    const uint4 v1 = __ldg(drow4 + 32 + lane);
    const uint4 v2 = __ldg(drow4 + 64 + lane);
    const uint4 v3 = __ldg(drow4 + 96 + lane);

    float xx = xa.x*xa.x + xa.y*xa.y + xa.z*xa.z + xa.w*xa.w
             + xb.x*xb.x + xb.y*xb.y + xb.z*xb.z + xb.w*xb.w;
#pragma unroll
    for (int off = 16; off; off >>= 1) xx += __shfl_xor_sync(0xffffffffu, xx, off);

    // rigorous margin: 12*2^-9 * ||x|| * ||e||max + slack   (||e|| < 1/64)
    const float margin = sqrtf(xx) * 0.015625f * (12.0f / 512.0f) + 3e-4f;
    const float thr = g_ymin[row] + margin;

    const uint32_t comp[16] = {v0.x, v0.y, v0.z, v0.w, v1.x, v1.y, v1.z, v1.w,
                               v2.x, v2.y, v2.z, v2.w, v3.x, v3.y, v3.z, v3.w};
    uint32_t mask = 0;
#pragma unroll
    for (int j = 0; j < 16; j++) {
        const float2 d = __bfloat1622float2(u2b(comp[j]));
        if (d.x <= thr) mask |= 1u << (2 * j);
        if (d.y <= thr) mask |= 1u << (2 * j + 1);
    }

    unsigned long long best = ~0ull;
    unsigned any = __ballot_sync(0xffffffffu, mask != 0);
    while (any) {
        const int lsrc = __ffs(any) - 1; any &= any - 1;
        uint32_t m = __shfl_sync(0xffffffffu, mask, lsrc);
        while (m) {
            const int bit = __ffs(m) - 1; m &= m - 1;
            const int code = ((bit >> 3) << 8) + (lsrc << 3) + (bit & 7);
            const float4* e4 = reinterpret_cast<const float4*>(emb + (size_t)code * DIM);
            const float4 ea = e4[lane], eb = e4[lane + 32];
            float s = xa.x * ea.x;
            s = fmaf(xa.y, ea.y, s); s = fmaf(xa.z, ea.z, s); s = fmaf(xa.w, ea.w, s);
            s = fmaf(xb.x, eb.x, s); s = fmaf(xb.y, eb.y, s);
            s = fmaf(xb.z, eb.z, s); s = fmaf(xb.w, eb.w, s);
#pragma unroll
            for (int off = 16; off; off >>= 1) s += __shfl_xor_sync(0xffffffffu, s, off);
            const float d2 = __fadd_rn(__fmaf_rn(-2.0f, s, xx), g_ee[code]);
            const unsigned long long key =
                ((unsigned long long)__float_as_uint(d2) << 32) | (unsigned)code;
            best = (key < best) ? key : best;
        }
    }
    if (lane == 0) g_win[row] = (int)(best & 0xffffffffu);
}

// ===========================================================================
// Gather + straight-through output + loss + fused finalize.
// FR=32 rows/block, dt-loop split across blockIdx.y in QUARTERS (4096 blocks,
// 2 sync-phases each).  Per-element arithmetic and output mapping identical
// to the proven kernel.
// ===========================================================================
#define FR 32

__global__ __launch_bounds__(256) void vq_gather_kernel(const float* __restrict__ emb,
                                                        float* __restrict__ out) {
    __shared__ int   s_idx[FR];
    __shared__ float tbuf[32][33];
    __shared__ float wsum[8];

    const int m0  = blockIdx.x * FR;
    const int dt0 = blockIdx.y * 64;      // this block's 64-dim quarter
    const int tid = threadIdx.x;
    if (tid < FR) s_idx[tid] = g_win[m0 + tid];
    __syncthreads();

    const int b_img = m0 >> 10;
    const int hw0   = m0 & (HWD - 1);
    const int dx = tid & 31;
    const int wy = tid >> 5;
    float lsum = 0.f;

    for (int dtl = 0; dtl < 64; dtl += 32) {
        const int dt = dt0 + dtl;
#pragma unroll
        for (int vv = 0; vv < FR; vv += 8) {
            const int v    = vv + wy;
            const int code = s_idx[v];
            const float e  = emb[code * DIM + dt + dx];
            const float x  = g_flat[(size_t)(m0 + v) * DIM + dt + dx];
            const float df = __fadd_rn(e, -x);
            lsum += df * df;
            tbuf[vv + wy][dx] = __fadd_rn(x, df);
        }
        __syncthreads();
#pragma unroll
        for (int dd = 0; dd < 32; dd += 8) {
            const int d = dt + dd + wy;
            out[(b_img * DIM + d) * HWD + hw0 + dx] = tbuf[dx][dd + wy];
        }
        __syncthreads();
    }

#pragma unroll
    for (int off = 16; off; off >>= 1) lsum += __shfl_xor_sync(0xffffffffu, lsum, off);
    if ((tid & 31) == 0) wsum[tid >> 5] = lsum;
    __syncthreads();
    if (tid == 0) {
        float tot = 0.f;
#pragma unroll
        for (int w = 0; w < 8; w++) tot += wsum[w];
        atomicAdd(&g_loss_sum, (double)tot);
        __threadfence();
        const unsigned done = atomicAdd(&g_done, 1u);
        if (done == (unsigned)(gridDim.x * gridDim.y - 1)) {
            __threadfence();
            const double total = atomicAdd(&g_loss_sum, 0.0);  // ordered read
            const float cb = (float)(total * (1.0 / (double)NELEM));
            out[NELEM + 0] = cb + 0.25f * cb;
            out[NELEM + 1] = cb;
            out[NELEM + 2] = cb;
            g_done = 0;  // reset for next graph replay
        }
    }
}

// ===========================================================================
extern "C" void kernel_launch(void* const* d_in, const int* in_sizes, int n_in,
                              void* d_out, int out_size) {
    const float* z   = (const float*)d_in[0];
    const float* emb = (const float*)d_in[1];
    if (n_in >= 2 && in_sizes[0] == NK * DIM && in_sizes[1] == NELEM) {
        const float* t = z; z = emb; emb = t;
    }
    float* out = (float*)d_out;

    cudaFuncSetAttribute(vq_gemm_kernel,
                         cudaFuncAttributeMaxDynamicSharedMemorySize, GEMM_SMEM);

    vq_transpose_kernel<<<dim3(HWD / 32, DIM / 32, NB), dim3(32, 8)>>>(z);
    vq_enorm_kernel<<<NK, 32>>>(emb);
    vq_gemm_kernel<<<NV / 128, 256, GEMM_SMEM>>>();
    vq_scan_kernel<<<NV / 8, 256>>>(emb);
    vq_gather_kernel<<<dim3(NV / FR, 4), 256>>>(emb, out);
}